// round 14
// baseline (speedup 1.0000x reference)
#include <cuda_runtime.h>
#include <cstdint>

// Problem constants
#define T_STEPS 1024
#define Hn      100
#define HROW    128   // padded h row stride (slots 0..99 valid, 100..127 pad)
#define BB      4     // batch rows per block
#define NTHREADS 256  // 128 ln-slots * 2 kc (8 warps, 2/SMSP -> reg cap 256)
#define NBLOCKS  128
#define BTOT     512

typedef unsigned long long ull;

// Scratch for h history: [t][n][b]  (~210MB, static .bss)
__device__ float g_hscr[T_STEPS][Hn][BTOT];

// ---------- f32x2 packed-math helpers ----------
__device__ __forceinline__ ull pack2(float lo, float hi) {
    ull r; asm("mov.b64 %0, {%1, %2};" : "=l"(r) : "f"(lo), "f"(hi)); return r;
}
__device__ __forceinline__ void unpack2(ull v, float& lo, float& hi) {
    asm("mov.b64 {%0, %1}, %2;" : "=f"(lo), "=f"(hi) : "l"(v));
}
__device__ __forceinline__ ull ffma2(ull a, ull b, ull c) {
    ull d; asm("fma.rn.f32x2 %0, %1, %2, %3;" : "=l"(d) : "l"(a), "l"(b), "l"(c)); return d;
}
__device__ __forceinline__ ull fadd2(ull a, ull b) {
    ull d; asm("add.rn.f32x2 %0, %1, %2;" : "=l"(d) : "l"(a), "l"(b)); return d;
}

// ---------- fast transcendentals (MUFU, ~1e-6 rel err) ----------
__device__ __forceinline__ float ex2a(float x) {
    float y; asm("ex2.approx.ftz.f32 %0, %1;" : "=f"(y) : "f"(x)); return y;
}
__device__ __forceinline__ float rcpa(float x) {
    float y; asm("rcp.approx.ftz.f32 %0, %1;" : "=f"(y) : "f"(x)); return y;
}

// Interleaved h layout inside one batch row (valid k packed into idx 0..99):
//   k = q*50 + r (q = k-half 0/1):
//     r < 48 : idx = (r/4)*8 + q*4 + (r%4)   (12 float4 chunks per half)
//     r >= 48: idx = 96 + q*2 + (r-48)        (float2 tail)
__device__ __forceinline__ int h_idx_of_k(int k) {
    int q = k / 50, r = k % 50;
    return (r < 48) ? ((r >> 2) * 8 + q * 4 + (r & 3)) : (96 + q * 2 + (r - 48));
}

// Thread layout: tid = ln*2 + kc, ln in [0,128) (ln>=100 inert), kc = k-half.
// Lane kc owns batches {2kc, 2kc+1} (two c-states in registers).
// 8 warps -> 2/SMSP -> reg cap 256: all 200 weight regs resident.
// FFMA2 floor: 2 warps x 400 inst x rt3 (3 distinct regs/bank) = 2400 cyc/SMSP.
__global__ void __launch_bounds__(NTHREADS, 1)
lstm_persistent_kernel(const float* __restrict__ input,   // [512][1024]
                       const float* __restrict__ W_ih,    // [400]
                       const float* __restrict__ W_hh,    // [400][100]
                       const float* __restrict__ b_ih,    // [400]
                       const float* __restrict__ b_hh)    // [400]
{
    __shared__ __align__(16) float h2[2][BB][HROW];        // double buffered
    __shared__ __align__(16) ulonglong2 s_gp1[128];        // {wih(i,f), bias(i,f)}
    __shared__ __align__(16) ulonglong2 s_gp2[128];        // {wih(g,o), bias(g,o)}

    const int tid  = threadIdx.x;
    const int ln   = tid >> 1;
    const int kc   = tid & 1;
    const bool valid = (ln < Hn);
    const int n = ln;
    const int nsafe = valid ? n : 0;
    const int bbase = blockIdx.x * BB;

    // ---- register-stationary weights: 25 k-pairs per gate (50 = 2*25) ----
    ull w[4][25];
    #pragma unroll
    for (int g = 0; g < 4; ++g) {
        const float* row = W_hh + (g * Hn + nsafe) * Hn;
        #pragma unroll
        for (int j = 0; j < 25; ++j) {
            const int k0 = kc * 50 + 2 * j;
            w[g][j] = valid ? pack2(row[k0], row[k0 + 1]) : 0ULL;
        }
    }
    // per-n wih/bias tables in SMEM
    if (kc == 0) {
        float wi = valid ? W_ih[n]            : 0.f;
        float wf = valid ? W_ih[Hn + n]       : 0.f;
        float wg = valid ? W_ih[2 * Hn + n]   : 0.f;
        float wo = valid ? W_ih[3 * Hn + n]   : 0.f;
        float bi = valid ? b_ih[n]          + b_hh[n]          : 0.f;
        float bf = valid ? b_ih[Hn + n]     + b_hh[Hn + n]     : 0.f;
        float bg = valid ? b_ih[2 * Hn + n] + b_hh[2 * Hn + n] : 0.f;
        float bo = valid ? b_ih[3 * Hn + n] + b_hh[3 * Hn + n] : 0.f;
        s_gp1[ln] = make_ulonglong2(pack2(wi, wf), pack2(bi, bf));
        s_gp2[ln] = make_ulonglong2(pack2(wg, wo), pack2(bg, bo));
    }

    // zero both h buffers
    for (int i = tid; i < 2 * BB * HROW; i += NTHREADS)
        (&h2[0][0][0])[i] = 0.0f;

    float c0 = 0.0f, c1 = 0.0f;     // c-states for owned batches 2kc, 2kc+1
    const float* __restrict__ xptrA = input + (bbase + 2 * kc) * T_STEPS;
    const float* __restrict__ xptrB = xptrA + T_STEPS;
    const int widx = valid ? h_idx_of_k(n) : ln;   // pads 100..111 for warp 6
    float* __restrict__ sptr = &g_hscr[0][nsafe][bbase + 2 * kc];

    // x double-buffer prefetch (hides LDG line-fill misses off the gate path)
    float xa_cur = xptrA[0];
    float xb_cur = xptrB[0];

    __syncthreads();

    for (int t = 0; t < T_STEPS; ++t) {
        const int p = t & 1;
        if (ln < 112) {   // warp 7 fully inert: skip body, keep barrier
            // prefetch next step's x immediately (consumed ~2000 cyc later)
            const int tn = (t + 1) & (T_STEPS - 1);
            const float xa_nxt = xptrA[tn];
            const float xb_nxt = xptrB[tn];

            const float* __restrict__ hb = &h2[p][0][0];

            ull G01[2], G23[2];
            #pragma unroll
            for (int b = 0; b < BB; ++b) {
                const float* rowp = hb + b * HROW;
                const ulonglong2* v =
                    reinterpret_cast<const ulonglong2*>(rowp + kc * 4);
                ull a0 = 0, a1 = 0, a2 = 0, a3 = 0;
                #pragma unroll
                for (int j = 0; j < 12; ++j) {
                    const ulonglong2 hp = v[j * 2];   // k-pairs 2j, 2j+1
                    a0 = ffma2(w[0][2 * j], hp.x, a0);
                    a1 = ffma2(w[1][2 * j], hp.x, a1);
                    a2 = ffma2(w[2][2 * j], hp.x, a2);
                    a3 = ffma2(w[3][2 * j], hp.x, a3);
                    a0 = ffma2(w[0][2 * j + 1], hp.y, a0);
                    a1 = ffma2(w[1][2 * j + 1], hp.y, a1);
                    a2 = ffma2(w[2][2 * j + 1], hp.y, a2);
                    a3 = ffma2(w[3][2 * j + 1], hp.y, a3);
                }
                // tail k-pair (r = 48,49) at idx 96 + kc*2
                const ull ht = *reinterpret_cast<const ull*>(rowp + 96 + kc * 2);
                a0 = ffma2(w[0][24], ht, a0);
                a1 = ffma2(w[1][24], ht, a1);
                a2 = ffma2(w[2][24], ht, a2);
                a3 = ffma2(w[3][24], ht, a3);
                // fold k-pair lanes, pack by gate pairs
                float lo, hi, s0, s1, s2, s3;
                unpack2(a0, lo, hi); s0 = lo + hi;
                unpack2(a1, lo, hi); s1 = lo + hi;
                unpack2(a2, lo, hi); s2 = lo + hi;
                unpack2(a3, lo, hi); s3 = lo + hi;
                const ull p01 = pack2(s0, s1);
                const ull p23 = pack2(s2, s3);
                // single xor-1 exchange with the other k-half
                const ull r01 = __shfl_xor_sync(0xffffffffu, p01, 1);
                const ull r23 = __shfl_xor_sync(0xffffffffu, p23, 1);
                if ((b >> 1) == kc) {
                    G01[b & 1] = fadd2(p01, r01);
                    G23[b & 1] = fadd2(p23, r23);
                }
            }

            // ---- gates for owned batches, interleaved for max MUFU ILP ----
            const ulonglong2 gp1 = s_gp1[ln];
            const ulonglong2 gp2 = s_gp2[ln];
            const ull xva = pack2(xa_cur, xa_cur);
            const ull xvb = pack2(xb_cur, xb_cur);
            const ull A0 = ffma2(xva, gp1.x, fadd2(G01[0], gp1.y));
            const ull B0 = ffma2(xva, gp2.x, fadd2(G23[0], gp2.y));
            const ull A1 = ffma2(xvb, gp1.x, fadd2(G01[1], gp1.y));
            const ull B1 = ffma2(xvb, gp2.x, fadd2(G23[1], gp2.y));
            float gi0, gf0, gg0, go0, gi1, gf1, gg1, go1;
            unpack2(A0, gi0, gf0); unpack2(B0, gg0, go0);
            unpack2(A1, gi1, gf1); unpack2(B1, gg1, go1);

            // batch all 8 ex2 (independent), then the rcp wave
            const float L1E = 1.4426950408889634f;
            const float ei0 = ex2a(-L1E * gi0);
            const float ef0 = ex2a(-L1E * gf0);
            const float eg0 = ex2a(-2.0f * L1E * gg0);
            const float eo0 = ex2a(-L1E * go0);
            const float ei1 = ex2a(-L1E * gi1);
            const float ef1 = ex2a(-L1E * gf1);
            const float eg1 = ex2a(-2.0f * L1E * gg1);
            const float eo1 = ex2a(-L1E * go1);
            const float ig0 = rcpa(1.0f + ei0);
            const float fg0 = rcpa(1.0f + ef0);
            const float tg0 = fmaf(2.0f, rcpa(1.0f + eg0), -1.0f);
            const float og0 = rcpa(1.0f + eo0);
            const float ig1 = rcpa(1.0f + ei1);
            const float fg1 = rcpa(1.0f + ef1);
            const float tg1 = fmaf(2.0f, rcpa(1.0f + eg1), -1.0f);
            const float og1 = rcpa(1.0f + eo1);

            c0 = fmaf(fg0, c0, ig0 * tg0);
            c1 = fmaf(fg1, c1, ig1 * tg1);
            const float ec0 = ex2a(-2.0f * L1E * c0);
            const float ec1 = ex2a(-2.0f * L1E * c1);
            const float h0 = og0 * fmaf(2.0f, rcpa(1.0f + ec0), -1.0f);
            const float h1 = og1 * fmaf(2.0f, rcpa(1.0f + ec1), -1.0f);

            // publish h into next buffer (rows = owned batches)
            float* hw = &h2[p ^ 1][0][0];
            hw[(2 * kc)     * HROW + widx] = h0;
            hw[(2 * kc + 1) * HROW + widx] = h1;
            // stream h history: one STG.64 (adjacent batches)
            if (valid)
                *reinterpret_cast<ull*>(sptr) = pack2(h0, h1);
            sptr += Hn * BTOT;

            xa_cur = xa_nxt;
            xb_cur = xb_nxt;
        }
        __syncthreads();
    }
}

// Output projection: out[b][t] = sum_n W_out[n] * h[t][n][b] + b_out.
// Fully parallel, DRAM-bound (measured 40us @ 68% DRAM).
__global__ void __launch_bounds__(BTOT, 2)
out_proj_kernel(const float* __restrict__ W_out,
                const float* __restrict__ b_out,
                float* __restrict__ out)
{
    const int t = blockIdx.x;
    const int b = threadIdx.x;
    float acc = b_out[0];
    const float* __restrict__ hp = &g_hscr[t][0][b];
    #pragma unroll 5
    for (int nn = 0; nn < Hn; ++nn)
        acc = fmaf(W_out[nn], hp[(size_t)nn * BTOT], acc);
    out[b * T_STEPS + t] = acc;
}

extern "C" void kernel_launch(void* const* d_in, const int* in_sizes, int n_in,
                              void* d_out, int out_size) {
    (void)in_sizes; (void)n_in; (void)out_size;
    const float* input = (const float*)d_in[0];
    const float* W_ih  = (const float*)d_in[1];
    const float* W_hh  = (const float*)d_in[2];
    const float* b_ih  = (const float*)d_in[3];
    const float* b_hh  = (const float*)d_in[4];
    const float* W_out = (const float*)d_in[5];
    const float* b_out = (const float*)d_in[6];
    float* out = (float*)d_out;

    lstm_persistent_kernel<<<NBLOCKS, NTHREADS>>>(input, W_ih, W_hh, b_ih, b_hh);
    out_proj_kernel<<<T_STEPS, BTOT>>>(W_out, b_out, out);
}

// round 16
// speedup vs baseline: 1.2800x; 1.2800x over previous
#include <cuda_runtime.h>
#include <cuda_bf16.h>
#include <cstdint>

#define T_STEPS 1024
#define Hn      100
#define KPAD    112            // 7 k16 steps; k 100..111 zero
#define ASTR    240            // A/B row stride bytes (60 words: bank-clean)
#define NTHREADS 256
#define NBLOCKS 128
#define BTOT    512
#define BB      4
#define GSTR    10             // gates row stride in floats (bank-clean)

// dynamic smem map
#define SM_A_HI 0
#define A_BYTES (400 * ASTR)                 // 96000
#define SM_A_LO (SM_A_HI + A_BYTES)          // 96000
#define SM_BT   (SM_A_LO + A_BYTES)          // 192000 (8 rows x ASTR)
#define SM_GS   (SM_BT + 8 * ASTR)           // 193920 (400 x GSTR floats)
#define SM_WIH  (SM_GS + 400 * GSTR * 4)     // 209920
#define SM_BIAS (SM_WIH + Hn * 16)           // 211520
#define SMEM_SIZE (SM_BIAS + Hn * 16)        // 213120

__device__ float g_hscr[T_STEPS][Hn][BTOT];

__device__ __forceinline__ float ex2a(float x) {
    float y; asm("ex2.approx.ftz.f32 %0, %1;" : "=f"(y) : "f"(x)); return y;
}
__device__ __forceinline__ float rcpa(float x) {
    float y; asm("rcp.approx.ftz.f32 %0, %1;" : "=f"(y) : "f"(x)); return y;
}
__device__ __forceinline__ float sigm(float x) {
    return rcpa(1.0f + ex2a(-1.4426950408889634f * x));
}
__device__ __forceinline__ float tanhx(float x) {
    return fmaf(2.0f, rcpa(1.0f + ex2a(-2.8853900817779268f * x)), -1.0f);
}

// m16n8k16 row.col f32.bf16.bf16.f32 — baseline PTX (sm_80+), no 'a' features
#define MMA(d0,d1,d2,d3,a0,a1,a2,a3,b0,b1)                                  \
    asm volatile("mma.sync.aligned.m16n8k16.row.col.f32.bf16.bf16.f32 "     \
                 "{%0,%1,%2,%3}, {%4,%5,%6,%7}, {%8,%9}, {%0,%1,%2,%3};"    \
                 : "+f"(d0), "+f"(d1), "+f"(d2), "+f"(d3)                   \
                 : "r"(a0), "r"(a1), "r"(a2), "r"(a3), "r"(b0), "r"(b1))

__device__ __forceinline__ float cell_step(const float* gS, const float4* wihS,
                                           const float4* biasS, int n, int b,
                                           float x, float& c) {
    const float4 wv = wihS[n], bv = biasS[n];
    float gi = gS[n * GSTR + b]         + gS[n * GSTR + b + 4];
    float gf = gS[(100 + n) * GSTR + b] + gS[(100 + n) * GSTR + b + 4];
    float gg = gS[(200 + n) * GSTR + b] + gS[(200 + n) * GSTR + b + 4];
    float go = gS[(300 + n) * GSTR + b] + gS[(300 + n) * GSTR + b + 4];
    gi = fmaf(x, wv.x, gi + bv.x);
    gf = fmaf(x, wv.y, gf + bv.y);
    gg = fmaf(x, wv.z, gg + bv.z);
    go = fmaf(x, wv.w, go + bv.w);
    c = fmaf(sigm(gf), c, sigm(gi) * tanhx(gg));
    return sigm(go) * tanhx(c);
}

// Per SM/step on tensor cores: D[400,8] = W[400,112] @ B[8,112]^T.
// B cols 0-3 = h_hi(batch), 4-7 = h_lo(batch); A passes hi then lo accumulate
// in fp32 D -> gate[b] = D[b] + D[b+4] = (Whi+Wlo)(hhi+hlo).
// 8 warps x 3 m16-tiles x 2 passes resident in regs (168); tile 24 from SMEM
// by warps 0 (hi -> gS cols 0-3) and 1 (lo -> cols 4-7), rows 384-399.
__global__ void __launch_bounds__(NTHREADS, 1)
lstm_mma_kernel(const float* __restrict__ input,
                const float* __restrict__ W_ih,
                const float* __restrict__ W_hh,
                const float* __restrict__ b_ih,
                const float* __restrict__ b_hh)
{
    extern __shared__ char smem[];
    const int tid = threadIdx.x;
    const int wid = tid >> 5;
    const int lane = tid & 31;
    const int lr = lane >> 2;          // fragment row-in-group
    const int lc = lane & 3;           // fragment col-group
    const int bbase = blockIdx.x * BB;

    // ---- build A_hi / A_lo (bf16 split of W_hh, row-major, k padded) ----
    for (int idx = tid; idx < 400 * KPAD; idx += NTHREADS) {
        const int r = idx / KPAD, k = idx - r * KPAD;
        const float wv = (k < Hn) ? W_hh[r * Hn + k] : 0.0f;
        const __nv_bfloat16 hi = __float2bfloat16(wv);
        const __nv_bfloat16 lo = __float2bfloat16(wv - __bfloat162float(hi));
        *(__nv_bfloat16*)(smem + SM_A_HI + r * ASTR + k * 2) = hi;
        *(__nv_bfloat16*)(smem + SM_A_LO + r * ASTR + k * 2) = lo;
    }
    // Bt zero (h(0)=0; k-pad cols stay zero forever)
    for (int idx = tid; idx < 8 * ASTR / 4; idx += NTHREADS)
        ((uint32_t*)(smem + SM_BT))[idx] = 0u;
    // gS zero (rows 0-383 cols 4-7 must stay zero)
    for (int idx = tid; idx < 400 * GSTR; idx += NTHREADS)
        ((float*)(smem + SM_GS))[idx] = 0.0f;
    if (tid < Hn) {
        const int n = tid;
        *(float4*)(smem + SM_WIH + n * 16) = make_float4(
            W_ih[n], W_ih[Hn + n], W_ih[2 * Hn + n], W_ih[3 * Hn + n]);
        *(float4*)(smem + SM_BIAS + n * 16) = make_float4(
            b_ih[n] + b_hh[n], b_ih[Hn + n] + b_hh[Hn + n],
            b_ih[2 * Hn + n] + b_hh[2 * Hn + n],
            b_ih[3 * Hn + n] + b_hh[3 * Hn + n]);
    }
    __syncthreads();

    // ---- resident A fragments: [pass][tile][ks][4] = 168 regs ----
    uint32_t af[2][3][7][4];
    #pragma unroll
    for (int p = 0; p < 2; ++p)
        #pragma unroll
        for (int i = 0; i < 3; ++i)
            #pragma unroll
            for (int ks = 0; ks < 7; ++ks) {
                const char* bp = smem + (p ? SM_A_LO : SM_A_HI) +
                    ((3 * wid + i) * 16 + lr) * ASTR + (lc * 2 + 16 * ks) * 2;
                af[p][i][ks][0] = *(const uint32_t*)(bp);
                af[p][i][ks][1] = *(const uint32_t*)(bp + 8 * ASTR);
                af[p][i][ks][2] = *(const uint32_t*)(bp + 16);
                af[p][i][ks][3] = *(const uint32_t*)(bp + 8 * ASTR + 16);
            }

    // epilogue cells: c1 = tid -> (n = tid>>2, b = tid&3); c2 = +256 (tid<144)
    const int n1 = tid >> 2, b1 = tid & 3;
    const int n2 = n1 + 64;
    const bool has2 = (tid < 144);
    float cs1 = 0.0f, cs2 = 0.0f;
    float* gS = (float*)(smem + SM_GS);
    const float4* wihS = (const float4*)(smem + SM_WIH);
    const float4* biasS = (const float4*)(smem + SM_BIAS);
    const float* __restrict__ xp = input + (bbase + b1) * T_STEPS;
    const char* btBase = smem + SM_BT + lr * ASTR + lc * 4;

    for (int t = 0; t < T_STEPS; ++t) {
        // ---- B fragments (lane lr = B-col, lc*2 = k base) ----
        uint32_t bf0[7], bf1[7];
        #pragma unroll
        for (int ks = 0; ks < 7; ++ks) {
            bf0[ks] = *(const uint32_t*)(btBase + 32 * ks);
            bf1[ks] = *(const uint32_t*)(btBase + 32 * ks + 16);
        }
        // ---- resident tiles: both passes accumulate into fp32 D ----
        #pragma unroll
        for (int i = 0; i < 3; ++i) {
            float d0 = 0.f, d1 = 0.f, d2 = 0.f, d3 = 0.f;
            #pragma unroll
            for (int ks = 0; ks < 7; ++ks)
                MMA(d0, d1, d2, d3, af[0][i][ks][0], af[0][i][ks][1],
                    af[0][i][ks][2], af[0][i][ks][3], bf0[ks], bf1[ks]);
            #pragma unroll
            for (int ks = 0; ks < 7; ++ks)
                MMA(d0, d1, d2, d3, af[1][i][ks][0], af[1][i][ks][1],
                    af[1][i][ks][2], af[1][i][ks][3], bf0[ks], bf1[ks]);
            // fold cols b / b+4 (lane-group lc xor 2), store gates cols 0-3
            const float f0 = d0 + __shfl_xor_sync(0xffffffffu, d0, 2);
            const float f1 = d1 + __shfl_xor_sync(0xffffffffu, d1, 2);
            const float f2 = d2 + __shfl_xor_sync(0xffffffffu, d2, 2);
            const float f3 = d3 + __shfl_xor_sync(0xffffffffu, d3, 2);
            if (lc < 2) {
                const int row = (3 * wid + i) * 16 + lr;
                *(float2*)(gS + row * GSTR + lc * 2) = make_float2(f0, f1);
                *(float2*)(gS + (row + 8) * GSTR + lc * 2) = make_float2(f2, f3);
            }
        }
        // ---- tile 24 (rows 384-399): warp 0 = hi pass, warp 1 = lo pass ----
        if (wid < 2) {
            float d0 = 0.f, d1 = 0.f, d2 = 0.f, d3 = 0.f;
            const char* ap = smem + (wid ? SM_A_LO : SM_A_HI) +
                             (384 + lr) * ASTR + lc * 4;
            #pragma unroll
            for (int ks = 0; ks < 7; ++ks) {
                const uint32_t a0 = *(const uint32_t*)(ap + 32 * ks);
                const uint32_t a1 = *(const uint32_t*)(ap + 32 * ks + 8 * ASTR);
                const uint32_t a2 = *(const uint32_t*)(ap + 32 * ks + 16);
                const uint32_t a3 = *(const uint32_t*)(ap + 32 * ks + 8 * ASTR + 16);
                MMA(d0, d1, d2, d3, a0, a1, a2, a3, bf0[ks], bf1[ks]);
            }
            const float f0 = d0 + __shfl_xor_sync(0xffffffffu, d0, 2);
            const float f1 = d1 + __shfl_xor_sync(0xffffffffu, d1, 2);
            const float f2 = d2 + __shfl_xor_sync(0xffffffffu, d2, 2);
            const float f3 = d3 + __shfl_xor_sync(0xffffffffu, d3, 2);
            if (lc < 2) {
                const int row = 384 + lr;
                const int co = lc * 2 + wid * 4;   // hi -> cols 0-3, lo -> 4-7
                *(float2*)(gS + row * GSTR + co) = make_float2(f0, f1);
                *(float2*)(gS + (row + 8) * GSTR + co) = make_float2(f2, f3);
            }
        }
        __syncthreads();

        // ---- epilogue: gates -> (c,h); rebuild Bt; stream h ----
        {
            const float xv = xp[t];
            const float h1 = cell_step(gS, wihS, biasS, n1, b1, xv, cs1);
            const __nv_bfloat16 h1h = __float2bfloat16(h1);
            const __nv_bfloat16 h1l =
                __float2bfloat16(h1 - __bfloat162float(h1h));
            *(__nv_bfloat16*)(smem + SM_BT + b1 * ASTR + n1 * 2) = h1h;
            *(__nv_bfloat16*)(smem + SM_BT + (b1 + 4) * ASTR + n1 * 2) = h1l;
            g_hscr[t][n1][bbase + b1] = h1;
            if (has2) {
                const float h2 = cell_step(gS, wihS, biasS, n2, b1, xv, cs2);
                const __nv_bfloat16 h2h = __float2bfloat16(h2);
                const __nv_bfloat16 h2l =
                    __float2bfloat16(h2 - __bfloat162float(h2h));
                *(__nv_bfloat16*)(smem + SM_BT + b1 * ASTR + n2 * 2) = h2h;
                *(__nv_bfloat16*)(smem + SM_BT + (b1 + 4) * ASTR + n2 * 2) = h2l;
                g_hscr[t][n2][bbase + b1] = h2;
            }
        }
        __syncthreads();
    }
}

// Output projection: DRAM-bound (measured ~40us @ 68% DRAM).
__global__ void __launch_bounds__(BTOT, 2)
out_proj_kernel(const float* __restrict__ W_out,
                const float* __restrict__ b_out,
                float* __restrict__ out)
{
    const int t = blockIdx.x;
    const int b = threadIdx.x;
    float acc = b_out[0];
    const float* __restrict__ hp = &g_hscr[t][0][b];
    #pragma unroll 5
    for (int nn = 0; nn < Hn; ++nn)
        acc = fmaf(W_out[nn], hp[(size_t)nn * BTOT], acc);
    out[b * T_STEPS + t] = acc;
}

extern "C" void kernel_launch(void* const* d_in, const int* in_sizes, int n_in,
                              void* d_out, int out_size) {
    (void)in_sizes; (void)n_in; (void)out_size;
    const float* input = (const float*)d_in[0];
    const float* W_ih  = (const float*)d_in[1];
    const float* W_hh  = (const float*)d_in[2];
    const float* b_ih  = (const float*)d_in[3];
    const float* b_hh  = (const float*)d_in[4];
    const float* W_out = (const float*)d_in[5];
    const float* b_out = (const float*)d_in[6];
    float* out = (float*)d_out;

    cudaFuncSetAttribute(lstm_mma_kernel,
                         cudaFuncAttributeMaxDynamicSharedMemorySize, SMEM_SIZE);
    lstm_mma_kernel<<<NBLOCKS, NTHREADS, SMEM_SIZE>>>(
        input, W_ih, W_hh, b_ih, b_hh);
    out_proj_kernel<<<T_STEPS, BTOT>>>(W_out, b_out, out);
}